// round 15
// baseline (speedup 1.0000x reference)
#include <cuda_runtime.h>
#include <cuda_bf16.h>
#include <cuda_fp16.h>
#include <cstdint>

#define B_ 32
#define CIN 256
#define CC 64
#define HS 64
#define PS 4096         // 64*64
#define HT 14
#define PT 196          // 14*14
#define NG 32           // groups (2 channels per group)

typedef unsigned long long ull;

// packed fp32x2 helpers (SASS FFMA2)
#define FMA2(d, a, b) asm("fma.rn.f32x2 %0, %1, %2, %0;" : "+l"(d) : "l"(a), "l"(b))
__device__ __forceinline__ ull PK(float lo, float hi) {
    ull r; asm("mov.b64 %0, {%1, %2};" : "=l"(r) : "f"(lo), "f"(hi)); return r;
}
__device__ __forceinline__ void UPK(float& lo, float& hi, ull v) {
    asm("mov.b64 {%0, %1}, %2;" : "=f"(lo), "=f"(hi) : "l"(v));
}

// cp.async helpers
__device__ __forceinline__ uint32_t smem_u32(const void* p) {
    return (uint32_t)__cvta_generic_to_shared(p);
}
__device__ __forceinline__ void cp16(uint32_t dst, const void* src) {
    asm volatile("cp.async.ca.shared.global [%0], [%1], 16;\n" :: "r"(dst), "l"(src));
}
__device__ __forceinline__ void cp16z(uint32_t dst, const void* src, uint32_t sz) {
    asm volatile("cp.async.ca.shared.global [%0], [%1], 16, %2;\n" :: "r"(dst), "l"(src), "r"(sz));
}
#define CP_COMMIT asm volatile("cp.async.commit_group;\n")
#define CP_WAIT0  asm volatile("cp.async.wait_group 0;\n")
#define CP_WAIT1  asm volatile("cp.async.wait_group 1;\n")

// ---- mma.sync / ldmatrix helpers ----
__device__ __forceinline__ void ldsm4(uint32_t* r, uint32_t addr) {
    asm volatile("ldmatrix.sync.aligned.m8n8.x4.shared.b16 {%0,%1,%2,%3}, [%4];"
        : "=r"(r[0]), "=r"(r[1]), "=r"(r[2]), "=r"(r[3]) : "r"(addr));
}
__device__ __forceinline__ void mma16816h(float* d, const uint32_t* a, const uint32_t* b) {
    asm volatile(
        "mma.sync.aligned.m16n8k16.row.col.f32.f16.f16.f32 "
        "{%0,%1,%2,%3}, {%4,%5,%6,%7}, {%8,%9}, {%0,%1,%2,%3};"
        : "+f"(d[0]), "+f"(d[1]), "+f"(d[2]), "+f"(d[3])
        : "r"(a[0]), "r"(a[1]), "r"(a[2]), "r"(a[3]), "r"(b[0]), "r"(b[1]));
}
#define SWZB(x) ((x) ^ (((x) >> 3) & 0x70))

// ---------------- device scratch ----------------
__device__ float g_s_pre[B_*CC*PS];
__device__ float g_corr[B_*CC*PS];
__device__ float g_y_pre[B_*CC*PS];
__device__ __half g_bT_hi[(size_t)B_*PS*CC];   // px-major corr, fp16 hi
__device__ __half g_bT_lo[(size_t)B_*PS*CC];   // px-major corr, fp16 lo
__device__ float g_tglobal[B_*CC];
__device__ float g_tkernel[B_*CC*49];
__device__ float g_part_s[B_*NG*32*2];
__device__ float g_part_y[B_*CC*128*2];        // per (b,c,yt*4+wn) sum/sumsq

// ---------------- kernel 1: FUSED conv1x1-search GEMM + template path ----------------
__global__ void __launch_bounds__(256) k_fused(
        const float* __restrict__ sf, const float* __restrict__ ws,
        const float* __restrict__ tf, const float* __restrict__ wt,
        const float* __restrict__ gw, const float* __restrict__ gb) {
    __shared__ __align__(16) char buf[49152];
    int tid = threadIdx.x;
    int blk = blockIdx.x;

    if (blk < 1024) {
        float* As0 = (float*)buf;              // [2][2048]
        float* Bs0 = (float*)(buf + 16384);    // [2][4096]
        int tile = blk & 31, b = blk >> 5;
        int tx = tid & 31, ty = tid >> 5;

        auto issue = [&](int s, int bufi) {
            int k0 = s * 32;
            float* Bs = Bs0 + bufi*4096;
            float* As = As0 + bufi*2048;
#pragma unroll
            for (int i = 0; i < 4; i++) {
                int t = tid*4 + i;
                int kk = t >> 5, j4 = (t & 31) << 2;
                cp16(smem_u32(Bs + kk*128 + j4),
                     sf + ((size_t)b*CIN + k0 + kk)*PS + tile*128 + j4);
            }
#pragma unroll
            for (int i = 0; i < 2; i++) {
                int slot = tid*2 + i;
                int o = slot >> 3, c4 = (slot & 7) << 2;
                cp16(smem_u32(As + o*32 + c4), ws + o*CIN + k0 + c4);
            }
            CP_COMMIT;
        };

        ull acc[8][2];
#pragma unroll
        for (int i = 0; i < 8; i++) { acc[i][0] = 0ULL; acc[i][1] = 0ULL; }

        issue(0, 0);
        for (int s = 0; s < 8; s++) {
            int cur = s & 1;
            if (s < 7) { issue(s+1, 1-cur); CP_WAIT1; }
            else       { CP_WAIT0; }
            __syncthreads();
            float* Bs = Bs0 + cur*4096;
            float* As = As0 + cur*2048;
#pragma unroll
            for (int kk = 0; kk < 32; kk++) {
                float4 bv = *(const float4*)(Bs + kk*128 + tx*4);
                ull b0 = PK(bv.x, bv.y), b1 = PK(bv.z, bv.w);
#pragma unroll
                for (int i = 0; i < 8; i++) {
                    float w = As[(ty*8 + i)*32 + kk];
                    ull a = PK(w, w);
                    FMA2(acc[i][0], a, b0);
                    FMA2(acc[i][1], a, b1);
                }
            }
            __syncthreads();
        }

        float gs[4], gss[4];
#pragma unroll
        for (int q = 0; q < 4; q++) { gs[q] = 0.f; gss[q] = 0.f; }
#pragma unroll
        for (int i = 0; i < 8; i++) {
            int o = ty*8 + i;
            float f0, f1, f2, f3;
            UPK(f0, f1, acc[i][0]);
            UPK(f2, f3, acc[i][1]);
            *(float4*)&g_s_pre[((size_t)b*CC + o)*PS + tile*128 + tx*4] =
                make_float4(f0, f1, f2, f3);
            int q = i >> 1;
            gs[q]  += f0 + f1 + f2 + f3;
            gss[q] += f0*f0 + f1*f1 + f2*f2 + f3*f3;
        }
#pragma unroll
        for (int q = 0; q < 4; q++) {
#pragma unroll
            for (int off = 16; off; off >>= 1) {
                gs[q]  += __shfl_down_sync(0xffffffffu, gs[q],  off);
                gss[q] += __shfl_down_sync(0xffffffffu, gss[q], off);
            }
        }
        if (tx == 0) {
#pragma unroll
            for (int q = 0; q < 4; q++) {
                int g = ty*4 + q;
                g_part_s[((b*NG + g)*32 + tile)*2 + 0] = gs[q];
                g_part_s[((b*NG + g)*32 + tile)*2 + 1] = gss[q];
            }
        }
        return;
    }

    // ---- template path ----
    {
        int tb = blk - 1024;
        int b = tb >> 2;
        int o0 = (tb & 3) * 16;
        float* wsm = (float*)buf;
        float* pre = (float*)(buf + 18432);
        float* s_mean = (float*)(buf + 30976);
        float* s_rstd = (float*)(buf + 31040);

        for (int idx = tid; idx < 4096; idx += 256) {
            int c = idx & 255, o = idx >> 8;
            wsm[c*18 + o] = wt[(o0+o)*CIN + c];
        }
        __syncthreads();

        if (tid < PT) {
            ull acc[8];
#pragma unroll
            for (int i = 0; i < 8; i++) acc[i] = 0ULL;
            const float* x = tf + (size_t)b*CIN*PT + tid;
#pragma unroll 4
            for (int c = 0; c < CIN; c++) {
                float xv = __ldg(x + c*PT);
                ull xd = PK(xv, xv);
#pragma unroll
                for (int i = 0; i < 8; i++) {
                    ull w = *(const ull*)&wsm[c*18 + 2*i];
                    FMA2(acc[i], w, xd);
                }
            }
#pragma unroll
            for (int i = 0; i < 8; i++) {
                float f0, f1; UPK(f0, f1, acc[i]);
                pre[(2*i)*PT + tid]   = f0;
                pre[(2*i+1)*PT + tid] = f1;
            }
        }
        __syncthreads();

        int warp = tid >> 5, lane = tid & 31;
        {
            int g = warp;
            float s = 0.f, ss = 0.f;
            const float* base = pre + g*2*PT;
            for (int i = lane; i < 2*PT; i += 32) { float v = base[i]; s += v; ss += v*v; }
#pragma unroll
            for (int off = 16; off; off >>= 1) {
                s  += __shfl_down_sync(0xffffffffu, s,  off);
                ss += __shfl_down_sync(0xffffffffu, ss, off);
            }
            if (lane == 0) {
                float m = s / (float)(2*PT);
                float var = ss / (float)(2*PT) - m*m;
                s_mean[g] = m; s_rstd[g] = rsqrtf(var + 1e-5f);
            }
        }
        __syncthreads();

        for (int idx = tid; idx < 16*PT; idx += 256) {
            int c = idx / PT; int g = c >> 1;
            float v = fmaf((pre[idx] - s_mean[g]) * s_rstd[g], gw[o0+c], gb[o0+c]);
            pre[idx] = fmaxf(v, 0.f);
        }
        __syncthreads();

        for (int c = warp; c < 16; c += 8) {
            float s = 0.f;
            for (int i = lane; i < PT; i += 32) s += pre[c*PT + i];
#pragma unroll
            for (int off = 16; off; off >>= 1) s += __shfl_down_sync(0xffffffffu, s, off);
            if (lane == 0) g_tglobal[b*CC + o0 + c] = s * (1.f/(float)PT);
        }
        for (int idx = tid; idx < 16*49; idx += 256) {
            int c = idx / 49, k = idx % 49, kh = k / 7, kw = k % 7;
            const float* p = pre + c*PT + (2*kh)*HT + 2*kw;
            g_tkernel[(b*CC + o0 + c)*49 + k] = 0.25f*(p[0] + p[1] + p[HT] + p[HT+1]);
        }
    }
}

// ---------------- kernel 2: correlation (GN stats folded in) ----------------
__global__ void __launch_bounds__(256) k_corr(const float* __restrict__ gsw,
                                              const float* __restrict__ gsb) {
    __shared__ float tile[70*72];
    __shared__ float tk[49];
    __shared__ float s_scsh[2];
    int bc = blockIdx.x;
    int b = bc >> 6, c = bc & 63, g = c >> 1;
    int tid = threadIdx.x;
    if (tid < 32) {
        float s  = g_part_s[((b*NG + g)*32 + tid)*2 + 0];
        float ss = g_part_s[((b*NG + g)*32 + tid)*2 + 1];
#pragma unroll
        for (int off = 16; off; off >>= 1) {
            s  += __shfl_down_sync(0xffffffffu, s,  off);
            ss += __shfl_down_sync(0xffffffffu, ss, off);
        }
        if (tid == 0) {
            float m = s * (1.f/8192.f);
            float var = ss * (1.f/8192.f) - m*m;
            float r = rsqrtf(var + 1e-5f);
            float scale = r * gsw[c];
            s_scsh[0] = scale;
            s_scsh[1] = gsb[c] - m*scale;
        }
    }
    if (tid < 49) tk[tid] = g_tkernel[bc*49 + tid];
    __syncthreads();
    float sc = s_scsh[0], sh = s_scsh[1], tg = g_tglobal[bc];

    const float* sp = g_s_pre + (size_t)bc*PS;
    for (int idx = tid; idx < 4900; idx += 256) {
        int rr = idx / 70, col = idx - rr*70;
        int r = rr - 3, cx = col - 3;
        float v = 0.f;
        if ((unsigned)r < 64u && (unsigned)cx < 64u)
            v = fmaxf(fmaf(sp[r*64 + cx], sc, sh), 0.f);
        tile[rr*72 + col] = v;
    }
    __syncthreads();
    float* dst = g_corr + (size_t)bc*PS;
#pragma unroll
    for (int it = 0; it < 2; it++) {
        int u = tid + it*256;
        int y = u >> 3, x8 = (u & 7) << 3;
        float a[8];
#pragma unroll
        for (int j = 0; j < 8; j++) a[j] = 0.f;
#pragma unroll
        for (int kh = 0; kh < 7; kh++) {
            const float* row = tile + (y+kh)*72 + x8;
            float rv[16];
            *(float4*)&rv[0]  = *(const float4*)(row);
            *(float4*)&rv[4]  = *(const float4*)(row + 4);
            *(float4*)&rv[8]  = *(const float4*)(row + 8);
            *(float4*)&rv[12] = *(const float4*)(row + 12);
            if (kh == 3) {
#pragma unroll
                for (int j = 0; j < 8; j++) a[j] = fmaf(tg, rv[j+3], a[j]);
            }
#pragma unroll
            for (int kw = 0; kw < 7; kw++) {
                float w = tk[kh*7 + kw];
#pragma unroll
                for (int j = 0; j < 8; j++) a[j] = fmaf(w, rv[kw + j], a[j]);
            }
        }
        float* d = dst + y*64 + x8;
        *(float4*)d       = make_float4(a[0], a[1], a[2], a[3]);
        *(float4*)(d + 4) = make_float4(a[4], a[5], a[6], a[7]);
    }
}

// ---------------- kernel 3: transpose corr -> px-major fp16 hi/lo ----------------
__global__ void __launch_bounds__(256) k_tr() {
    __shared__ float ts[64*133];
    int blk = blockIdx.x;
    int b = blk >> 5, p0 = (blk & 31) << 7;
    int tid = threadIdx.x;
#pragma unroll
    for (int i = 0; i < 8; i++) {
        int idx = tid + i*256;
        int c = idx >> 5, j4 = (idx & 31) << 2;
        float4 v = *(const float4*)&g_corr[((size_t)(b*64 + c))*PS + p0 + j4];
        float* t = &ts[c*133 + j4];
        t[0] = v.x; t[1] = v.y; t[2] = v.z; t[3] = v.w;
    }
    __syncthreads();
    int px = tid >> 1, ch = (tid & 1) * 32;
    size_t P = (size_t)b*PS + p0 + px;
    unsigned short hv[32], lv[32];
#pragma unroll
    for (int cc = 0; cc < 32; cc++) {
        float v = ts[(ch + cc)*133 + px];
        __half h = __float2half(v);
        float hf = __half2float(h);
        __half l = __float2half(v - hf);
        hv[cc] = *(unsigned short*)&h;
        lv[cc] = *(unsigned short*)&l;
    }
    uint4* dh = (uint4*)(g_bT_hi + P*64 + ch);
    uint4* dl = (uint4*)(g_bT_lo + P*64 + ch);
#pragma unroll
    for (int q = 0; q < 4; q++) {
        uint4 u, w;
        u.x = hv[q*8+0] | (hv[q*8+1] << 16); u.y = hv[q*8+2] | (hv[q*8+3] << 16);
        u.z = hv[q*8+4] | (hv[q*8+5] << 16); u.w = hv[q*8+6] | (hv[q*8+7] << 16);
        w.x = lv[q*8+0] | (lv[q*8+1] << 16); w.y = lv[q*8+2] | (lv[q*8+3] << 16);
        w.z = lv[q*8+4] | (lv[q*8+5] << 16); w.w = lv[q*8+6] | (lv[q*8+7] << 16);
        dh[q] = u; dl[q] = w;
    }
}

// ---------------- kernel 4: conv3x3 via mma.sync (fp16 2-term, retiled, dbl-buffered) ----------------
#define W_BYTES   73728          // 9 taps * 64o * 128B (hi only)
#define X_PART    33792          // 264 rows * 128B (one precision part)
#define X_BUF     (2*X_PART)     // hi + lo
#define CMMA_SMEM (W_BYTES + 2*X_BUF + 128)

__global__ void __launch_bounds__(256) k_cmma(const float* __restrict__ wp1) {
    extern __shared__ char dyn[];
    uint32_t dynb = smem_u32(dyn);
    uint32_t Wb = (dynb + 127) & ~127u;
    uint32_t Xb0 = Wb + W_BYTES;
    char* Wg = dyn + (Wb - dynb);
    int tid = threadIdx.x;
    int wid = tid >> 5, lane = tid & 31;

    // W prep: fp16 hi only, per-tap [64o][64c] swizzled (wp1 = 36864 floats)
    for (int idx = tid; idx < 36864; idx += 256) {
        float w = __ldg(wp1 + idx);
        int o = idx / 576, rem = idx - o*576;
        int c = rem / 9, k = rem - c*9;
        __half h = __float2half(w);
        *(__half*)(Wg + k*8192 + SWZB((uint32_t)(o*128 + c*2))) = h;
    }

    int wm = wid & 1, wn = wid >> 1;            // 2 M-warps x 4 N-warps
    int om0 = wm << 5;                          // 32 o per M-warp
    int yrow = wn >> 1, xbase = (wn & 1) << 5;  // 32 px per N-warp
    int arow = lane & 15;
    int achunk = (lane & 16) ? 16 : 0;
    int brlane = lane & 7;
    int bsel8 = (lane >> 4) & 1;
    int bchunk = (lane & 8) ? 16 : 0;

    auto issueX = [&](int t, int pb) {
        int b = t >> 5, y0 = (t & 31) << 1;
        uint32_t Xb = Xb0 + pb*X_BUF;
        for (int idx = tid; idx < 4224; idx += 256) {
            int part = idx / 2112, rem = idx - part*2112;
            int srow = rem / 528, r3 = rem - srow*528;
            int slot = r3 >> 3, unit = r3 & 7;
            int y = y0 + srow - 1, x = slot - 1;
            bool ok = ((unsigned)y < 64u) && ((unsigned)x < 64u);
            int yy = ok ? y : 0, xx = ok ? x : 0;
            const __half* src = (part ? g_bT_lo : g_bT_hi)
                + (((size_t)b*PS + yy*64 + xx) << 6) + unit*8;
            uint32_t dst = Xb + part*X_PART + SWZB((uint32_t)(((srow*66 + slot) << 7) + unit*16));
            cp16z(dst, src, ok ? 16u : 0u);
        }
        CP_COMMIT;
    };

    int t0 = blockIdx.x;
    if (t0 < 1024) issueX(t0, 0);
    __syncthreads();          // W stores visible

    int pb = 0;
    for (int t = t0; t < 1024; t += gridDim.x, pb ^= 1) {
        int b = t >> 5, yt = t & 31, y0 = yt << 1;
        CP_WAIT0;
        __syncthreads();
        uint32_t Xb = Xb0 + pb*X_BUF;

        int tn = t + gridDim.x;
        if (tn < 1024) issueX(tn, pb ^ 1);   // overlap next load with compute

        float acc[2][4][4];
#pragma unroll
        for (int mi = 0; mi < 2; mi++)
#pragma unroll
            for (int nj = 0; nj < 4; nj++)
#pragma unroll
                for (int j = 0; j < 4; j++) acc[mi][nj][j] = 0.f;

        for (int dy = 0; dy < 3; dy++) {
            int srow = yrow + dy;
            for (int dx = 0; dx < 3; dx++) {
                uint32_t wtap = Wb + (dy*3 + dx)*8192;
#pragma unroll
                for (int ks = 0; ks < 4; ks++) {
                    uint32_t a0[4], a1[4];
                    ldsm4(a0, wtap + SWZB((uint32_t)((om0 + arow)*128 + ks*32 + achunk)));
                    ldsm4(a1, wtap + SWZB((uint32_t)((om0 + 16 + arow)*128 + ks*32 + achunk)));
#pragma unroll
                    for (int jj = 0; jj < 2; jj++) {
                        int slot = xbase + jj*16 + dx + bsel8*8 + brlane;
                        uint32_t boff = SWZB((uint32_t)(((srow*66 + slot) << 7) + ks*32 + bchunk));
                        uint32_t bh[4], bl[4];
                        ldsm4(bh, Xb + boff);
                        ldsm4(bl, Xb + X_PART + boff);
                        mma16816h(acc[0][jj*2+0], a0, bh+0);
                        mma16816h(acc[0][jj*2+0], a0, bl+0);
                        mma16816h(acc[0][jj*2+1], a0, bh+2);
                        mma16816h(acc[0][jj*2+1], a0, bl+2);
                        mma16816h(acc[1][jj*2+0], a1, bh+0);
                        mma16816h(acc[1][jj*2+0], a1, bl+0);
                        mma16816h(acc[1][jj*2+1], a1, bh+2);
                        mma16816h(acc[1][jj*2+1], a1, bl+2);
                    }
                }
            }
        }

        // epilogue: direct STG + GN partials (x-half per warp)
        int q = lane >> 2, tx2 = (lane & 3) << 1;
        int y = y0 + yrow;
        int ti = (yt << 2) + wn;
#pragma unroll
        for (int mi = 0; mi < 2; mi++) {
            int oa = om0 + mi*16 + q, ob = oa + 8;
            float* da = &g_y_pre[((size_t)(b*64 + oa))*PS + y*64 + xbase];
            float* db = &g_y_pre[((size_t)(b*64 + ob))*PS + y*64 + xbase];
            float s0 = 0.f, ss0 = 0.f, s1 = 0.f, ss1 = 0.f;
#pragma unroll
            for (int nj = 0; nj < 4; nj++) {
                int x = nj*8 + tx2;
                float* a = acc[mi][nj];
                *(float2*)(da + x) = make_float2(a[0], a[1]);
                *(float2*)(db + x) = make_float2(a[2], a[3]);
                s0 += a[0] + a[1]; ss0 += a[0]*a[0] + a[1]*a[1];
                s1 += a[2] + a[3]; ss1 += a[2]*a[2] + a[3]*a[3];
            }
            s0 += __shfl_xor_sync(0xffffffffu, s0, 1); s0 += __shfl_xor_sync(0xffffffffu, s0, 2);
            ss0 += __shfl_xor_sync(0xffffffffu, ss0, 1); ss0 += __shfl_xor_sync(0xffffffffu, ss0, 2);
            s1 += __shfl_xor_sync(0xffffffffu, s1, 1); s1 += __shfl_xor_sync(0xffffffffu, s1, 2);
            ss1 += __shfl_xor_sync(0xffffffffu, ss1, 1); ss1 += __shfl_xor_sync(0xffffffffu, ss1, 2);
            if ((lane & 3) == 0) {
                g_part_y[((b*64 + oa)*128 + ti)*2 + 0] = s0;
                g_part_y[((b*64 + oa)*128 + ti)*2 + 1] = ss0;
                g_part_y[((b*64 + ob)*128 + ti)*2 + 0] = s1;
                g_part_y[((b*64 + ob)*128 + ti)*2 + 1] = ss1;
            }
        }
    }
}

// ---------------- kernel 5: GN(y) + relu + final 1x1 + bias ----------------
__global__ void __launch_bounds__(256) k_out(
        const float* __restrict__ wp2, const float* __restrict__ bp2,
        const float* __restrict__ gpw, const float* __restrict__ gpb,
        float* __restrict__ out) {
    __shared__ float su[64], sq[64], scs[64], shs[64];
    int blk = blockIdx.x;
    int b = blk >> 4, p0 = (blk & 15) << 8;
    int tid = threadIdx.x;
    if (tid < 64) {
        int c = tid;
        float s = 0.f, ss = 0.f;
#pragma unroll 8
        for (int t = 0; t < 128; t++) {
            s  += g_part_y[((b*64 + c)*128 + t)*2 + 0];
            ss += g_part_y[((b*64 + c)*128 + t)*2 + 1];
        }
        su[c] = s; sq[c] = ss;
    }
    __syncthreads();
    if (tid < 64) {
        int c = tid;
        float S = su[c] + su[c^1], SS = sq[c] + sq[c^1];
        float m = S * (1.f/8192.f);
        float var = SS * (1.f/8192.f) - m*m;
        float r = rsqrtf(var + 1e-5f);
        float scale = r * gpw[c];
        scs[c] = scale;
        shs[c] = gpb[c] - m*scale;
    }
    __syncthreads();
    float acc = bp2[0];
    const float* yp = g_y_pre + (size_t)(b*CC)*PS + p0 + tid;
#pragma unroll 8
    for (int o = 0; o < 64; o++) {
        float v = fmaxf(fmaf(yp[(size_t)o*PS], scs[o], shs[o]), 0.f);
        acc = fmaf(wp2[o], v, acc);
    }
    out[b*PS + p0 + tid] = acc;
}

// ---------------- launch ----------------
extern "C" void kernel_launch(void* const* d_in, const int* in_sizes, int n_in,
                              void* d_out, int out_size) {
    const float* tf  = (const float*)d_in[0];
    const float* sf  = (const float*)d_in[1];
    const float* wt  = (const float*)d_in[2];
    const float* gtw = (const float*)d_in[3];
    const float* gtb = (const float*)d_in[4];
    const float* ws  = (const float*)d_in[5];
    const float* gsw = (const float*)d_in[6];
    const float* gsb = (const float*)d_in[7];
    const float* wp1 = (const float*)d_in[8];
    const float* gpw = (const float*)d_in[9];
    const float* gpb = (const float*)d_in[10];
    const float* wp2 = (const float*)d_in[11];
    const float* bp2 = (const float*)d_in[12];
    float* out = (float*)d_out;

    cudaFuncSetAttribute(k_cmma, cudaFuncAttributeMaxDynamicSharedMemorySize, CMMA_SMEM);

    k_fused<<<1152, 256>>>(sf, ws, tf, wt, gtw, gtb);    // 0
    k_corr<<<2048, 256>>>(gsw, gsb);                     // 1
    k_tr<<<1024, 256>>>();                               // 2
    k_cmma<<<148, 256, CMMA_SMEM>>>(wp1);                // 3  (ncu capture slot)
    k_out<<<512, 256>>>(wp2, bp2, gpw, gpb, out);        // 4
}

// round 16
// speedup vs baseline: 1.4013x; 1.4013x over previous
#include <cuda_runtime.h>
#include <cuda_bf16.h>
#include <cuda_fp16.h>
#include <cstdint>

#define B_ 32
#define CIN 256
#define CC 64
#define HS 64
#define PS 4096         // 64*64
#define HT 14
#define PT 196          // 14*14
#define NG 32           // groups (2 channels per group)

typedef unsigned long long ull;

// packed fp32x2 helpers (SASS FFMA2)
#define FMA2(d, a, b) asm("fma.rn.f32x2 %0, %1, %2, %0;" : "+l"(d) : "l"(a), "l"(b))
__device__ __forceinline__ ull PK(float lo, float hi) {
    ull r; asm("mov.b64 %0, {%1, %2};" : "=l"(r) : "f"(lo), "f"(hi)); return r;
}
__device__ __forceinline__ void UPK(float& lo, float& hi, ull v) {
    asm("mov.b64 {%0, %1}, %2;" : "=f"(lo), "=f"(hi) : "l"(v));
}

// cp.async helpers
__device__ __forceinline__ uint32_t smem_u32(const void* p) {
    return (uint32_t)__cvta_generic_to_shared(p);
}
__device__ __forceinline__ void cp16(uint32_t dst, const void* src) {
    asm volatile("cp.async.ca.shared.global [%0], [%1], 16;\n" :: "r"(dst), "l"(src));
}
__device__ __forceinline__ void cp16z(uint32_t dst, const void* src, uint32_t sz) {
    asm volatile("cp.async.ca.shared.global [%0], [%1], 16, %2;\n" :: "r"(dst), "l"(src), "r"(sz));
}
#define CP_COMMIT asm volatile("cp.async.commit_group;\n")
#define CP_WAIT0  asm volatile("cp.async.wait_group 0;\n")
#define CP_WAIT1  asm volatile("cp.async.wait_group 1;\n")

// ---- mma.sync / ldmatrix helpers ----
__device__ __forceinline__ void ldsm4(uint32_t* r, uint32_t addr) {
    asm volatile("ldmatrix.sync.aligned.m8n8.x4.shared.b16 {%0,%1,%2,%3}, [%4];"
        : "=r"(r[0]), "=r"(r[1]), "=r"(r[2]), "=r"(r[3]) : "r"(addr));
}
__device__ __forceinline__ void mma16816h(float* d, const uint32_t* a, const uint32_t* b) {
    asm volatile(
        "mma.sync.aligned.m16n8k16.row.col.f32.f16.f16.f32 "
        "{%0,%1,%2,%3}, {%4,%5,%6,%7}, {%8,%9}, {%0,%1,%2,%3};"
        : "+f"(d[0]), "+f"(d[1]), "+f"(d[2]), "+f"(d[3])
        : "r"(a[0]), "r"(a[1]), "r"(a[2]), "r"(a[3]), "r"(b[0]), "r"(b[1]));
}
#define SWZB(x) ((x) ^ (((x) >> 3) & 0x70))

// ---------------- device scratch ----------------
__device__ float g_s_pre[B_*CC*PS];
__device__ float g_corr[B_*CC*PS];
__device__ float g_y_pre[B_*CC*PS];
__device__ __half g_bT_hi[(size_t)B_*PS*CC];   // px-major corr, fp16 hi
__device__ __half g_bT_lo[(size_t)B_*PS*CC];   // px-major corr, fp16 lo
__device__ float g_tglobal[B_*CC];
__device__ float g_tkernel[B_*CC*49];
__device__ float g_part_s[B_*NG*32*2];
__device__ float g_part_y[B_*CC*256*2];        // per (b,c,yt*8+wn) sum/sumsq

// ---------------- kernel 1: FUSED conv1x1-search GEMM + template path ----------------
__global__ void __launch_bounds__(256) k_fused(
        const float* __restrict__ sf, const float* __restrict__ ws,
        const float* __restrict__ tf, const float* __restrict__ wt,
        const float* __restrict__ gw, const float* __restrict__ gb) {
    __shared__ __align__(16) char buf[49152];
    int tid = threadIdx.x;
    int blk = blockIdx.x;

    if (blk < 1024) {
        float* As0 = (float*)buf;              // [2][2048]
        float* Bs0 = (float*)(buf + 16384);    // [2][4096]
        int tile = blk & 31, b = blk >> 5;
        int tx = tid & 31, ty = tid >> 5;

        auto issue = [&](int s, int bufi) {
            int k0 = s * 32;
            float* Bs = Bs0 + bufi*4096;
            float* As = As0 + bufi*2048;
#pragma unroll
            for (int i = 0; i < 4; i++) {
                int t = tid*4 + i;
                int kk = t >> 5, j4 = (t & 31) << 2;
                cp16(smem_u32(Bs + kk*128 + j4),
                     sf + ((size_t)b*CIN + k0 + kk)*PS + tile*128 + j4);
            }
#pragma unroll
            for (int i = 0; i < 2; i++) {
                int slot = tid*2 + i;
                int o = slot >> 3, c4 = (slot & 7) << 2;
                cp16(smem_u32(As + o*32 + c4), ws + o*CIN + k0 + c4);
            }
            CP_COMMIT;
        };

        ull acc[8][2];
#pragma unroll
        for (int i = 0; i < 8; i++) { acc[i][0] = 0ULL; acc[i][1] = 0ULL; }

        issue(0, 0);
        for (int s = 0; s < 8; s++) {
            int cur = s & 1;
            if (s < 7) { issue(s+1, 1-cur); CP_WAIT1; }
            else       { CP_WAIT0; }
            __syncthreads();
            float* Bs = Bs0 + cur*4096;
            float* As = As0 + cur*2048;
#pragma unroll
            for (int kk = 0; kk < 32; kk++) {
                float4 bv = *(const float4*)(Bs + kk*128 + tx*4);
                ull b0 = PK(bv.x, bv.y), b1 = PK(bv.z, bv.w);
#pragma unroll
                for (int i = 0; i < 8; i++) {
                    float w = As[(ty*8 + i)*32 + kk];
                    ull a = PK(w, w);
                    FMA2(acc[i][0], a, b0);
                    FMA2(acc[i][1], a, b1);
                }
            }
            __syncthreads();
        }

        float gs[4], gss[4];
#pragma unroll
        for (int q = 0; q < 4; q++) { gs[q] = 0.f; gss[q] = 0.f; }
#pragma unroll
        for (int i = 0; i < 8; i++) {
            int o = ty*8 + i;
            float f0, f1, f2, f3;
            UPK(f0, f1, acc[i][0]);
            UPK(f2, f3, acc[i][1]);
            *(float4*)&g_s_pre[((size_t)b*CC + o)*PS + tile*128 + tx*4] =
                make_float4(f0, f1, f2, f3);
            int q = i >> 1;
            gs[q]  += f0 + f1 + f2 + f3;
            gss[q] += f0*f0 + f1*f1 + f2*f2 + f3*f3;
        }
#pragma unroll
        for (int q = 0; q < 4; q++) {
#pragma unroll
            for (int off = 16; off; off >>= 1) {
                gs[q]  += __shfl_down_sync(0xffffffffu, gs[q],  off);
                gss[q] += __shfl_down_sync(0xffffffffu, gss[q], off);
            }
        }
        if (tx == 0) {
#pragma unroll
            for (int q = 0; q < 4; q++) {
                int g = ty*4 + q;
                g_part_s[((b*NG + g)*32 + tile)*2 + 0] = gs[q];
                g_part_s[((b*NG + g)*32 + tile)*2 + 1] = gss[q];
            }
        }
        return;
    }

    // ---- template path ----
    {
        int tb = blk - 1024;
        int b = tb >> 2;
        int o0 = (tb & 3) * 16;
        float* wsm = (float*)buf;
        float* pre = (float*)(buf + 18432);
        float* s_mean = (float*)(buf + 30976);
        float* s_rstd = (float*)(buf + 31040);

        for (int idx = tid; idx < 4096; idx += 256) {
            int c = idx & 255, o = idx >> 8;
            wsm[c*18 + o] = wt[(o0+o)*CIN + c];
        }
        __syncthreads();

        if (tid < PT) {
            ull acc[8];
#pragma unroll
            for (int i = 0; i < 8; i++) acc[i] = 0ULL;
            const float* x = tf + (size_t)b*CIN*PT + tid;
#pragma unroll 4
            for (int c = 0; c < CIN; c++) {
                float xv = __ldg(x + c*PT);
                ull xd = PK(xv, xv);
#pragma unroll
                for (int i = 0; i < 8; i++) {
                    ull w = *(const ull*)&wsm[c*18 + 2*i];
                    FMA2(acc[i], w, xd);
                }
            }
#pragma unroll
            for (int i = 0; i < 8; i++) {
                float f0, f1; UPK(f0, f1, acc[i]);
                pre[(2*i)*PT + tid]   = f0;
                pre[(2*i+1)*PT + tid] = f1;
            }
        }
        __syncthreads();

        int warp = tid >> 5, lane = tid & 31;
        {
            int g = warp;
            float s = 0.f, ss = 0.f;
            const float* base = pre + g*2*PT;
            for (int i = lane; i < 2*PT; i += 32) { float v = base[i]; s += v; ss += v*v; }
#pragma unroll
            for (int off = 16; off; off >>= 1) {
                s  += __shfl_down_sync(0xffffffffu, s,  off);
                ss += __shfl_down_sync(0xffffffffu, ss, off);
            }
            if (lane == 0) {
                float m = s / (float)(2*PT);
                float var = ss / (float)(2*PT) - m*m;
                s_mean[g] = m; s_rstd[g] = rsqrtf(var + 1e-5f);
            }
        }
        __syncthreads();

        for (int idx = tid; idx < 16*PT; idx += 256) {
            int c = idx / PT; int g = c >> 1;
            float v = fmaf((pre[idx] - s_mean[g]) * s_rstd[g], gw[o0+c], gb[o0+c]);
            pre[idx] = fmaxf(v, 0.f);
        }
        __syncthreads();

        for (int c = warp; c < 16; c += 8) {
            float s = 0.f;
            for (int i = lane; i < PT; i += 32) s += pre[c*PT + i];
#pragma unroll
            for (int off = 16; off; off >>= 1) s += __shfl_down_sync(0xffffffffu, s, off);
            if (lane == 0) g_tglobal[b*CC + o0 + c] = s * (1.f/(float)PT);
        }
        for (int idx = tid; idx < 16*49; idx += 256) {
            int c = idx / 49, k = idx % 49, kh = k / 7, kw = k % 7;
            const float* p = pre + c*PT + (2*kh)*HT + 2*kw;
            g_tkernel[(b*CC + o0 + c)*49 + k] = 0.25f*(p[0] + p[1] + p[HT] + p[HT+1]);
        }
    }
}

// ---------------- kernel 2: correlation (GN stats folded in) ----------------
__global__ void __launch_bounds__(256) k_corr(const float* __restrict__ gsw,
                                              const float* __restrict__ gsb) {
    __shared__ float tile[70*72];
    __shared__ float tk[49];
    __shared__ float s_scsh[2];
    int bc = blockIdx.x;
    int b = bc >> 6, c = bc & 63, g = c >> 1;
    int tid = threadIdx.x;
    if (tid < 32) {
        float s  = g_part_s[((b*NG + g)*32 + tid)*2 + 0];
        float ss = g_part_s[((b*NG + g)*32 + tid)*2 + 1];
#pragma unroll
        for (int off = 16; off; off >>= 1) {
            s  += __shfl_down_sync(0xffffffffu, s,  off);
            ss += __shfl_down_sync(0xffffffffu, ss, off);
        }
        if (tid == 0) {
            float m = s * (1.f/8192.f);
            float var = ss * (1.f/8192.f) - m*m;
            float r = rsqrtf(var + 1e-5f);
            float scale = r * gsw[c];
            s_scsh[0] = scale;
            s_scsh[1] = gsb[c] - m*scale;
        }
    }
    if (tid < 49) tk[tid] = g_tkernel[bc*49 + tid];
    __syncthreads();
    float sc = s_scsh[0], sh = s_scsh[1], tg = g_tglobal[bc];

    const float* sp = g_s_pre + (size_t)bc*PS;
    for (int idx = tid; idx < 4900; idx += 256) {
        int rr = idx / 70, col = idx - rr*70;
        int r = rr - 3, cx = col - 3;
        float v = 0.f;
        if ((unsigned)r < 64u && (unsigned)cx < 64u)
            v = fmaxf(fmaf(sp[r*64 + cx], sc, sh), 0.f);
        tile[rr*72 + col] = v;
    }
    __syncthreads();
    float* dst = g_corr + (size_t)bc*PS;
#pragma unroll
    for (int it = 0; it < 2; it++) {
        int u = tid + it*256;
        int y = u >> 3, x8 = (u & 7) << 3;
        float a[8];
#pragma unroll
        for (int j = 0; j < 8; j++) a[j] = 0.f;
#pragma unroll
        for (int kh = 0; kh < 7; kh++) {
            const float* row = tile + (y+kh)*72 + x8;
            float rv[16];
            *(float4*)&rv[0]  = *(const float4*)(row);
            *(float4*)&rv[4]  = *(const float4*)(row + 4);
            *(float4*)&rv[8]  = *(const float4*)(row + 8);
            *(float4*)&rv[12] = *(const float4*)(row + 12);
            if (kh == 3) {
#pragma unroll
                for (int j = 0; j < 8; j++) a[j] = fmaf(tg, rv[j+3], a[j]);
            }
#pragma unroll
            for (int kw = 0; kw < 7; kw++) {
                float w = tk[kh*7 + kw];
#pragma unroll
                for (int j = 0; j < 8; j++) a[j] = fmaf(w, rv[kw + j], a[j]);
            }
        }
        float* d = dst + y*64 + x8;
        *(float4*)d       = make_float4(a[0], a[1], a[2], a[3]);
        *(float4*)(d + 4) = make_float4(a[4], a[5], a[6], a[7]);
    }
}

// ---------------- kernel 3: transpose corr -> px-major fp16 hi/lo ----------------
__global__ void __launch_bounds__(256) k_tr() {
    __shared__ float ts[64*133];
    int blk = blockIdx.x;
    int b = blk >> 5, p0 = (blk & 31) << 7;
    int tid = threadIdx.x;
#pragma unroll
    for (int i = 0; i < 8; i++) {
        int idx = tid + i*256;
        int c = idx >> 5, j4 = (idx & 31) << 2;
        float4 v = *(const float4*)&g_corr[((size_t)(b*64 + c))*PS + p0 + j4];
        float* t = &ts[c*133 + j4];
        t[0] = v.x; t[1] = v.y; t[2] = v.z; t[3] = v.w;
    }
    __syncthreads();
    int px = tid >> 1, ch = (tid & 1) * 32;
    size_t P = (size_t)b*PS + p0 + px;
    unsigned short hv[32], lv[32];
#pragma unroll
    for (int cc = 0; cc < 32; cc++) {
        float v = ts[(ch + cc)*133 + px];
        __half h = __float2half(v);
        float hf = __half2float(h);
        __half l = __float2half(v - hf);
        hv[cc] = *(unsigned short*)&h;
        lv[cc] = *(unsigned short*)&l;
    }
    uint4* dh = (uint4*)(g_bT_hi + P*64 + ch);
    uint4* dl = (uint4*)(g_bT_lo + P*64 + ch);
#pragma unroll
    for (int q = 0; q < 4; q++) {
        uint4 u, w;
        u.x = hv[q*8+0] | (hv[q*8+1] << 16); u.y = hv[q*8+2] | (hv[q*8+3] << 16);
        u.z = hv[q*8+4] | (hv[q*8+5] << 16); u.w = hv[q*8+6] | (hv[q*8+7] << 16);
        w.x = lv[q*8+0] | (lv[q*8+1] << 16); w.y = lv[q*8+2] | (lv[q*8+3] << 16);
        w.z = lv[q*8+4] | (lv[q*8+5] << 16); w.w = lv[q*8+6] | (lv[q*8+7] << 16);
        dh[q] = u; dl[q] = w;
    }
}

// ---------------- kernel 4: conv3x3 via mma.sync (fp16 2-term, 512 thr, 2Mx8N) ----------------
#define W_BYTES   73728          // 9 taps * 64o * 128B (fp16 hi)
#define X_PART    33792          // 264 rows * 128B
#define X_BUF     (2*X_PART)
#define CMMA_SMEM (W_BYTES + 2*X_BUF + 128)

__global__ void __launch_bounds__(512) k_cmma(const float* __restrict__ wp1) {
    extern __shared__ char dyn[];
    uint32_t dynb = smem_u32(dyn);
    uint32_t Wb = (dynb + 127) & ~127u;
    uint32_t Xb0 = Wb + W_BYTES;
    char* Wg = dyn + (Wb - dynb);
    int tid = threadIdx.x;
    int wid = tid >> 5, lane = tid & 31;

    // W prep: fp16 hi, per-tap [64o][64c] swizzled (wp1 = 36864 floats)
    for (int idx = tid; idx < 36864; idx += 512) {
        float w = __ldg(wp1 + idx);
        int o = idx / 576, rem = idx - o*576;
        int c = rem / 9, k = rem - c*9;
        *(__half*)(Wg + k*8192 + SWZB((uint32_t)(o*128 + c*2))) = __float2half(w);
    }

    int wm = wid & 1, wn = wid >> 1;            // 2 M-warps x 8 N-warps
    int om0 = wm << 5;                          // 32 o per M-warp
    int yrow = wn >> 2, xbase = (wn & 3) << 4;  // 16 px per N-warp
    int arow = lane & 15;
    int achunk = (lane & 16) ? 16 : 0;
    int brlane = lane & 7;
    int bsel8 = (lane >> 4) & 1;
    int bchunk = (lane & 8) ? 16 : 0;

    auto issueX = [&](int t, int pb) {
        int b = t >> 5, y0 = (t & 31) << 1;
        uint32_t Xb = Xb0 + pb*X_BUF;
        for (int idx = tid; idx < 4224; idx += 512) {
            int part = idx / 2112, rem = idx - part*2112;
            int srow = rem / 528, r3 = rem - srow*528;
            int slot = r3 >> 3, unit = r3 & 7;
            int y = y0 + srow - 1, x = slot - 1;
            bool ok = ((unsigned)y < 64u) && ((unsigned)x < 64u);
            int yy = ok ? y : 0, xx = ok ? x : 0;
            const __half* src = (part ? g_bT_lo : g_bT_hi)
                + (((size_t)b*PS + yy*64 + xx) << 6) + unit*8;
            uint32_t dst = Xb + part*X_PART + SWZB((uint32_t)(((srow*66 + slot) << 7) + unit*16));
            cp16z(dst, src, ok ? 16u : 0u);
        }
        CP_COMMIT;
    };

    int t0 = blockIdx.x;
    if (t0 < 1024) issueX(t0, 0);
    __syncthreads();          // W stores + first X issue ordered

    int pb = 0;
    for (int t = t0; t < 1024; t += gridDim.x, pb ^= 1) {
        int b = t >> 5, yt = t & 31, y0 = yt << 1;
        CP_WAIT0;
        __syncthreads();      // X[pb] ready; everyone done with X[pb^1]
        uint32_t Xb = Xb0 + pb*X_BUF;

        int tn = t + gridDim.x;
        if (tn < 1024) issueX(tn, pb ^ 1);   // overlap next load with compute

        float acc[2][2][4];
#pragma unroll
        for (int mi = 0; mi < 2; mi++)
#pragma unroll
            for (int nj = 0; nj < 2; nj++)
#pragma unroll
                for (int j = 0; j < 4; j++) acc[mi][nj][j] = 0.f;

        for (int dy = 0; dy < 3; dy++) {
            int srow = yrow + dy;
            for (int dx = 0; dx < 3; dx++) {
                uint32_t wtap = Wb + (dy*3 + dx)*8192;
#pragma unroll
                for (int ks = 0; ks < 4; ks++) {
                    uint32_t a0[4], a1[4];
                    ldsm4(a0, wtap + SWZB((uint32_t)((om0 + arow)*128 + ks*32 + achunk)));
                    ldsm4(a1, wtap + SWZB((uint32_t)((om0 + 16 + arow)*128 + ks*32 + achunk)));
                    int slot = xbase + dx + bsel8*8 + brlane;
                    uint32_t boff = SWZB((uint32_t)(((srow*66 + slot) << 7) + ks*32 + bchunk));
                    uint32_t bh[4], bl[4];
                    ldsm4(bh, Xb + boff);
                    ldsm4(bl, Xb + X_PART + boff);
                    mma16816h(acc[0][0], a0, bh+0);
                    mma16816h(acc[0][0], a0, bl+0);
                    mma16816h(acc[0][1], a0, bh+2);
                    mma16816h(acc[0][1], a0, bl+2);
                    mma16816h(acc[1][0], a1, bh+0);
                    mma16816h(acc[1][0], a1, bl+0);
                    mma16816h(acc[1][1], a1, bh+2);
                    mma16816h(acc[1][1], a1, bl+2);
                }
            }
        }

        // epilogue: direct STG + GN partials (16 px per warp)
        int q = lane >> 2, tx2 = (lane & 3) << 1;
        int y = y0 + yrow;
        int ti = (yt << 3) + wn;
#pragma unroll
        for (int mi = 0; mi < 2; mi++) {
            int oa = om0 + mi*16 + q, ob = oa + 8;
            float* da = &g_y_pre[((size_t)(b*64 + oa))*PS + y*64 + xbase];
            float* db = &g_y_pre[((size_t)(b*64 + ob))*PS + y*64 + xbase];
            float s0 = 0.f, ss0 = 0.f, s1 = 0.f, ss1 = 0.f;
#pragma unroll
            for (int nj = 0; nj < 2; nj++) {
                int x = nj*8 + tx2;
                float* a = acc[mi][nj];
                *(float2*)(da + x) = make_float2(a[0], a[1]);
                *(float2*)(db + x) = make_float2(a[2], a[3]);
                s0 += a[0] + a[1]; ss0 += a[0]*a[0] + a[1]*a[1];
                s1 += a[2] + a[3]; ss1 += a[2]*a[2] + a[3]*a[3];
            }
            s0 += __shfl_xor_sync(0xffffffffu, s0, 1); s0 += __shfl_xor_sync(0xffffffffu, s0, 2);
            ss0 += __shfl_xor_sync(0xffffffffu, ss0, 1); ss0 += __shfl_xor_sync(0xffffffffu, ss0, 2);
            s1 += __shfl_xor_sync(0xffffffffu, s1, 1); s1 += __shfl_xor_sync(0xffffffffu, s1, 2);
            ss1 += __shfl_xor_sync(0xffffffffu, ss1, 1); ss1 += __shfl_xor_sync(0xffffffffu, ss1, 2);
            if ((lane & 3) == 0) {
                g_part_y[((b*64 + oa)*256 + ti)*2 + 0] = s0;
                g_part_y[((b*64 + oa)*256 + ti)*2 + 1] = ss0;
                g_part_y[((b*64 + ob)*256 + ti)*2 + 0] = s1;
                g_part_y[((b*64 + ob)*256 + ti)*2 + 1] = ss1;
            }
        }
    }
}

// ---------------- kernel 5: GN(y) + relu + final 1x1 + bias ----------------
__global__ void __launch_bounds__(256) k_out(
        const float* __restrict__ wp2, const float* __restrict__ bp2,
        const float* __restrict__ gpw, const float* __restrict__ gpb,
        float* __restrict__ out) {
    __shared__ float su4[256], sq4[256];
    __shared__ float scs[64], shs[64];
    int blk = blockIdx.x;
    int b = blk >> 4, p0 = (blk & 15) << 8;
    int tid = threadIdx.x;
    {
        int c = tid >> 2, pp = tid & 3;
        float s = 0.f, ss = 0.f;
        const float* p = &g_part_y[((b*64 + c)*256 + pp*64)*2];
#pragma unroll 8
        for (int t = 0; t < 64; t++) {
            s  += p[2*t + 0];
            ss += p[2*t + 1];
        }
        su4[tid] = s; sq4[tid] = ss;
    }
    __syncthreads();
    if (tid < 64) {
        int c = tid;
        float S = 0.f, SS = 0.f;
#pragma unroll
        for (int j = 0; j < 4; j++) {
            S  += su4[c*4 + j] + su4[(c^1)*4 + j];
            SS += sq4[c*4 + j] + sq4[(c^1)*4 + j];
        }
        float m = S * (1.f/8192.f);
        float var = SS * (1.f/8192.f) - m*m;
        float r = rsqrtf(var + 1e-5f);
        float scale = r * gpw[c];
        scs[c] = scale;
        shs[c] = gpb[c] - m*scale;
    }
    __syncthreads();
    float acc = bp2[0];
    const float* yp = g_y_pre + (size_t)(b*CC)*PS + p0 + tid;
#pragma unroll 8
    for (int o = 0; o < 64; o++) {
        float v = fmaxf(fmaf(yp[(size_t)o*PS], scs[o], shs[o]), 0.f);
        acc = fmaf(wp2[o], v, acc);
    }
    out[b*PS + p0 + tid] = acc;
}

// ---------------- launch ----------------
extern "C" void kernel_launch(void* const* d_in, const int* in_sizes, int n_in,
                              void* d_out, int out_size) {
    const float* tf  = (const float*)d_in[0];
    const float* sf  = (const float*)d_in[1];
    const float* wt  = (const float*)d_in[2];
    const float* gtw = (const float*)d_in[3];
    const float* gtb = (const float*)d_in[4];
    const float* ws  = (const float*)d_in[5];
    const float* gsw = (const float*)d_in[6];
    const float* gsb = (const float*)d_in[7];
    const float* wp1 = (const float*)d_in[8];
    const float* gpw = (const float*)d_in[9];
    const float* gpb = (const float*)d_in[10];
    const float* wp2 = (const float*)d_in[11];
    const float* bp2 = (const float*)d_in[12];
    float* out = (float*)d_out;

    cudaFuncSetAttribute(k_cmma, cudaFuncAttributeMaxDynamicSharedMemorySize, CMMA_SMEM);

    k_fused<<<1152, 256>>>(sf, ws, tf, wt, gtw, gtb);    // 0
    k_corr<<<2048, 256>>>(gsw, gsb);                     // 1
    k_tr<<<1024, 256>>>();                               // 2
    k_cmma<<<148, 512, CMMA_SMEM>>>(wp1);                // 3  (ncu capture slot)
    k_out<<<512, 256>>>(wp2, bp2, gpw, gpb, out);        // 4
}